// round 16
// baseline (speedup 1.0000x reference)
#include <cuda_runtime.h>
#include <cuda_fp16.h>
#include <math.h>
#include <stdint.h>

#define B_  2
#define S_  2048
#define D_  256
#define H_  8
#define C_  32
#define OUT_ 256
#define WIN_ 32
#define M_  (B_ * S_)

// -------- device scratch --------
__device__ __align__(16) __half g_Wh[3 * 256 * 256];  // QT^T, KT^T, VT^T hi ([n][k])
__device__ __align__(16) __half g_Wl[3 * 256 * 256];  // lo
__device__ __align__(16) __half g_Qh[M_ * D_], g_Ql[M_ * D_];
__device__ __align__(16) __half g_K [M_ * D_];
__device__ __align__(16) __half g_V [M_ * D_];
__device__ __align__(16) float  g_G [M_ * D_];
__device__ __align__(16) __half g_O [M_ * D_];

// ================= helpers =================
__device__ __forceinline__ uint32_t smem_u32(const void* p) {
    uint32_t a;
    asm("{ .reg .u64 t; cvta.to.shared.u64 t, %1; cvt.u32.u64 %0, t; }" : "=r"(a) : "l"(p));
    return a;
}
#define LDM_X4(r, addr) \
    asm volatile("ldmatrix.sync.aligned.m8n8.x4.shared.b16 {%0,%1,%2,%3}, [%4];" \
        : "=r"((r)[0]), "=r"((r)[1]), "=r"((r)[2]), "=r"((r)[3]) : "r"(addr))
#define LDM_X2(r, addr) \
    asm volatile("ldmatrix.sync.aligned.m8n8.x2.shared.b16 {%0,%1}, [%2];" \
        : "=r"((r)[0]), "=r"((r)[1]) : "r"(addr))
#define LDM_X2_T(r, addr) \
    asm volatile("ldmatrix.sync.aligned.m8n8.x2.trans.shared.b16 {%0,%1}, [%2];" \
        : "=r"((r)[0]), "=r"((r)[1]) : "r"(addr))
#define MMA_F16(c, a, b) \
    asm volatile("mma.sync.aligned.m16n8k16.row.col.f32.f16.f16.f32 " \
        "{%0,%1,%2,%3}, {%4,%5,%6,%7}, {%8,%9}, {%0,%1,%2,%3};" \
        : "+f"((c)[0]), "+f"((c)[1]), "+f"((c)[2]), "+f"((c)[3]) \
        : "r"((a)[0]), "r"((a)[1]), "r"((a)[2]), "r"((a)[3]), "r"((b)[0]), "r"((b)[1]))
#define CP_ASYNC16(dst, src) \
    asm volatile("cp.async.cg.shared.global [%0], [%1], 16;" :: "r"(dst), "l"(src))
#define CP_COMMIT() asm volatile("cp.async.commit_group;" ::: "memory")
#define CP_WAIT(n)  asm volatile("cp.async.wait_group %0;" :: "n"(n) : "memory")

__device__ __forceinline__ void split2h(float a, float b, uint32_t& h, uint32_t& l) {
    __half2 hi2 = __floats2half2_rn(a, b);
    float ra = a - __low2float(hi2);
    float rb = b - __high2float(hi2);
    __half2 lo2 = __floats2half2_rn(ra, rb);
    h = *reinterpret_cast<uint32_t*>(&hi2);
    l = *reinterpret_cast<uint32_t*>(&lo2);
}

// ================= tiny prep: transpose+split QT/KT/VT only =================
__global__ void prep_w(const float* __restrict__ QT, const float* __restrict__ KT,
                       const float* __restrict__ VT) {
    int t = blockIdx.x;                 // 0..191
    int z = t >> 6;
    int ky = (t >> 3) & 7;
    int nx = t & 7;
    const float* src = (z == 0) ? QT : (z == 1) ? KT : VT;
    size_t base = (size_t)z * 65536;
    __shared__ float tr[32][33];
    int tx = threadIdx.x & 31, ty = threadIdx.x >> 5;
    int k0 = ky * 32, n0 = nx * 32;
#pragma unroll
    for (int r = 0; r < 4; r++)
        tr[ty + r * 8][tx] = src[(size_t)(k0 + ty + r * 8) * 256 + n0 + tx];
    __syncthreads();
#pragma unroll
    for (int r = 0; r < 4; r++) {
        int n = n0 + ty + r * 8, k = k0 + tx;
        float v = tr[tx][ty + r * 8];
        __half h = __float2half(v);
        g_Wh[base + (size_t)n * 256 + k] = h;
        g_Wl[base + (size_t)n * 256 + k] = __float2half(v - __half2float(h));
    }
}

// ================= GEMM: BM=64,BN=64,BK=128, fully prefetched, in-kernel cvt =================
#define G_ROW  272
#define GBM    64
#define GBN    64
#define STAGE_ ((GBM + 2 * GBN) * G_ROW)    // 52224
#define SMEM_GEMM (2 * STAGE_)              // 104448

// MODE: 0 = split half out, 1 = f32+bias+sigmoid, 2 = f32+bias, 3 = single half out
// ACVT: 1 = A is fp32 (convert during staging); 0 = A fp16 via cp.async
// BCVT: 1 = B is fp32 [n][k] (split during staging); 0 = B pre-split fp16 via cp.async
template <int MODE, int ACVT, int BCVT>
__device__ __forceinline__ void gemm_core(const void* Ap,
                                          const void* Bhp, const void* Blp,
                                          const float* __restrict__ bias,
                                          float* __restrict__ Yf,
                                          __half* __restrict__ Yh, __half* __restrict__ Yl,
                                          int m0, int n0) {
    extern __shared__ char smem[];
    const uint32_t sb = smem_u32(smem);
    const int tid = threadIdx.x, wid = tid >> 5, lane = tid & 31;
    const int warp_m = wid & 1, warp_n = wid >> 1;   // 2 x 4 warps, warp tile 32x16
    const int lm_row = lane & 15, lm_chunk = (lane >> 4) * 16;

    // ---- issue all cp.async first (non-converted operands, both chunks) ----
    if (!ACVT) {
        const __half* A16 = (const __half*)Ap;
#pragma unroll
        for (int kc = 0; kc < 2; kc++)
            for (int task = tid; task < 1024; task += 256) {
                int row = task >> 4, ch = task & 15;
                CP_ASYNC16(sb + kc * STAGE_ + row * G_ROW + ch * 16,
                           A16 + (size_t)(m0 + row) * 256 + kc * 128 + ch * 8);
            }
    }
    if (!BCVT) {
        const __half* Bh16 = (const __half*)Bhp;
        const __half* Bl16 = (const __half*)Blp;
#pragma unroll
        for (int kc = 0; kc < 2; kc++)
            for (int task = tid; task < 2048; task += 256) {
                int half_sel = task >> 10;        // 0 = Bh, 1 = Bl
                int r = (task >> 4) & 63, ch = task & 15;
                const __half* s = (half_sel ? Bl16 : Bh16) + (size_t)(n0 + r) * 256 + kc * 128 + ch * 8;
                CP_ASYNC16(sb + kc * STAGE_ + (GBM + half_sel * GBN + r) * G_ROW + ch * 16, s);
            }
    }
    CP_COMMIT();

    // ---- converted operands: LDG fp32 -> cvt -> STS (overlaps with cp.async) ----
    if (ACVT) {
        const float* A32 = (const float*)Ap;
#pragma unroll
        for (int kc = 0; kc < 2; kc++)
            for (int task = tid; task < 2048; task += 256) {
                int row = task >> 5, c4 = task & 31;   // 32 float4 per 128-float row-chunk
                float4 v = *reinterpret_cast<const float4*>(
                    A32 + (size_t)(m0 + row) * 256 + kc * 128 + c4 * 4);
                __half2 a = __floats2half2_rn(v.x, v.y);
                __half2 b = __floats2half2_rn(v.z, v.w);
                *reinterpret_cast<uint2*>(smem + kc * STAGE_ + row * G_ROW + c4 * 8) =
                    make_uint2(*reinterpret_cast<uint32_t*>(&a), *reinterpret_cast<uint32_t*>(&b));
            }
    }
    if (BCVT) {
        const float* W32 = (const float*)Bhp;   // fp32 [n][k]
#pragma unroll
        for (int kc = 0; kc < 2; kc++)
            for (int task = tid; task < 2048; task += 256) {
                int row = task >> 5, c4 = task & 31;
                float4 v = *reinterpret_cast<const float4*>(
                    W32 + (size_t)(n0 + row) * 256 + kc * 128 + c4 * 4);
                uint32_t h0, l0, h1, l1;
                split2h(v.x, v.y, h0, l0);
                split2h(v.z, v.w, h1, l1);
                *reinterpret_cast<uint2*>(smem + kc * STAGE_ + (GBM + row) * G_ROW + c4 * 8) =
                    make_uint2(h0, h1);
                *reinterpret_cast<uint2*>(smem + kc * STAGE_ + (GBM + GBN + row) * G_ROW + c4 * 8) =
                    make_uint2(l0, l1);
            }
    }

    CP_WAIT(0);
    __syncthreads();

    // ---- MMA: 2 chunks x 8 k-steps, no further syncs ----
    float acc[2][2][4];
#pragma unroll
    for (int i = 0; i < 2; i++)
#pragma unroll
        for (int j = 0; j < 2; j++)
#pragma unroll
            for (int q = 0; q < 4; q++) acc[i][j][q] = 0.f;

#pragma unroll
    for (int kc = 0; kc < 2; kc++) {
        const uint32_t bb = sb + kc * STAGE_;
#pragma unroll
        for (int ks = 0; ks < 8; ks++) {
            const uint32_t kbyte = ks * 32 + lm_chunk;
            uint32_t a[2][4], bh[2][2], bl[2][2];
#pragma unroll
            for (int mf = 0; mf < 2; mf++) {
                uint32_t off = (uint32_t)((warp_m * 32 + mf * 16 + lm_row) * G_ROW) + kbyte;
                LDM_X4(a[mf], bb + off);
            }
            {
                uint32_t off = (uint32_t)((GBM + warp_n * 16 + lm_row) * G_ROW) + kbyte;
                uint32_t th[4], tl[4];
                LDM_X4(th, bb + off);
                LDM_X4(tl, bb + GBN * G_ROW + off);
                bh[0][0] = th[0]; bh[0][1] = th[2];
                bh[1][0] = th[1]; bh[1][1] = th[3];
                bl[0][0] = tl[0]; bl[0][1] = tl[2];
                bl[1][0] = tl[1]; bl[1][1] = tl[3];
            }
#pragma unroll
            for (int mf = 0; mf < 2; mf++)
#pragma unroll
                for (int nf = 0; nf < 2; nf++) {
                    MMA_F16(acc[mf][nf], a[mf], bh[nf]);
                    MMA_F16(acc[mf][nf], a[mf], bl[nf]);
                }
        }
    }

    // ---- epilogue ----
#pragma unroll
    for (int mf = 0; mf < 2; mf++) {
        int row = m0 + warp_m * 32 + mf * 16 + (lane >> 2);
#pragma unroll
        for (int nf = 0; nf < 2; nf++) {
            int col = n0 + warp_n * 16 + nf * 8 + (lane & 3) * 2;
            float v0 = acc[mf][nf][0], v1 = acc[mf][nf][1];
            float v2 = acc[mf][nf][2], v3 = acc[mf][nf][3];
            if (MODE == 1 || MODE == 2) {
                float b0 = bias[col], b1 = bias[col + 1];
                v0 += b0; v1 += b1; v2 += b0; v3 += b1;
                if (MODE == 1) {
                    v0 = 1.f / (1.f + __expf(-v0));
                    v1 = 1.f / (1.f + __expf(-v1));
                    v2 = 1.f / (1.f + __expf(-v2));
                    v3 = 1.f / (1.f + __expf(-v3));
                }
                *reinterpret_cast<float2*>(Yf + (size_t)row * 256 + col)       = make_float2(v0, v1);
                *reinterpret_cast<float2*>(Yf + (size_t)(row + 8) * 256 + col) = make_float2(v2, v3);
            } else if (MODE == 0) {
                uint32_t h0, l0, h1, l1;
                split2h(v0, v1, h0, l0);
                split2h(v2, v3, h1, l1);
                *reinterpret_cast<uint32_t*>(Yh + (size_t)row * 256 + col)       = h0;
                *reinterpret_cast<uint32_t*>(Yl + (size_t)row * 256 + col)       = l0;
                *reinterpret_cast<uint32_t*>(Yh + (size_t)(row + 8) * 256 + col) = h1;
                *reinterpret_cast<uint32_t*>(Yl + (size_t)(row + 8) * 256 + col) = l1;
            } else {
                __half2 a2 = __floats2half2_rn(v0, v1);
                __half2 b2 = __floats2half2_rn(v2, v3);
                *reinterpret_cast<uint32_t*>(Yh + (size_t)row * 256 + col)       = *reinterpret_cast<uint32_t*>(&a2);
                *reinterpret_cast<uint32_t*>(Yh + (size_t)(row + 8) * 256 + col) = *reinterpret_cast<uint32_t*>(&b2);
            }
        }
    }
}

__global__ void __launch_bounds__(256, 2)
proj_kernel(const float* __restrict__ Qin, const float* __restrict__ Kin,
            const float* __restrict__ Vin, const float* __restrict__ GW,
            const float* __restrict__ Gb) {
    int z = blockIdx.z;
    int m0 = blockIdx.y * GBM, n0 = blockIdx.x * GBN;
    const float* A = (z == 0) ? Qin : (z == 1) ? Kin : Vin;   // z==3 uses Vin
    if (z == 0)      gemm_core<0, 1, 0>(A, g_Wh,            g_Wl,            nullptr, nullptr, g_Qh, g_Ql, m0, n0);
    else if (z == 1) gemm_core<3, 1, 0>(A, g_Wh + 65536,    g_Wl + 65536,    nullptr, nullptr, g_K, nullptr, m0, n0);
    else if (z == 2) gemm_core<3, 1, 0>(A, g_Wh + 2*65536,  g_Wl + 2*65536,  nullptr, nullptr, g_V, nullptr, m0, n0);
    else             gemm_core<1, 1, 1>(A, GW, nullptr, Gb, g_G, nullptr, nullptr, m0, n0);
}

__global__ void __launch_bounds__(256, 2)
out_kernel(const float* __restrict__ OW, const float* __restrict__ Ob,
           float* __restrict__ out) {
    gemm_core<2, 0, 1>(g_O, OW, nullptr, Ob, out, nullptr, nullptr,
                       blockIdx.y * GBM, blockIdx.x * GBN);
}

// ================= fp16 tensor-core local-window attention (R9/R12) =================
#define A_QH 0
#define A_QL 2560
#define A_K  5120
#define A_V  12800
#define A_PH 20480
#define A_PL 27136
#define A_RED 33792
#define A_TOTAL 34816
#define QK_ROW 80
#define VT_ROW 208

__global__ void __launch_bounds__(256)
attn_kernel() {
    __shared__ __align__(16) char sm[A_TOTAL];
    const uint32_t sb = smem_u32(sm);
    float* red = reinterpret_cast<float*>(sm + A_RED);

    const int b = blockIdx.z, h = blockIdx.y, s0 = blockIdx.x * 32;
    const int tid = threadIdx.x, wid = tid >> 5, lane = tid & 31;
    const int lm_row = lane & 15, lm_chunk = (lane >> 4) * 16;

    for (int i = tid; i < 384; i += 256) {
        int row = i >> 2, ch = i & 3;
        int t = s0 - 32 + row;
        uint4 vk = make_uint4(0, 0, 0, 0), vv = vk;
        if (t >= 0 && t < S_) {
            size_t e = (size_t)(b * S_ + t) * 256 + h * 32 + ch * 8;
            vk = *reinterpret_cast<const uint4*>(g_K + e);
            vv = *reinterpret_cast<const uint4*>(g_V + e);
        }
        *reinterpret_cast<uint4*>(sm + A_K + row * QK_ROW + ch * 16) = vk;
        *reinterpret_cast<uint4*>(sm + A_V + row * QK_ROW + ch * 16) = vv;
    }
    for (int i = tid; i < 128; i += 256) {
        int row = i >> 2, ch = i & 3;
        size_t e = (size_t)(b * S_ + s0 + row) * 256 + h * 32 + ch * 8;
        *reinterpret_cast<uint4*>(sm + A_QH + row * QK_ROW + ch * 16) =
            *reinterpret_cast<const uint4*>(g_Qh + e);
        *reinterpret_cast<uint4*>(sm + A_QL + row * QK_ROW + ch * 16) =
            *reinterpret_cast<const uint4*>(g_Ql + e);
    }
    __syncthreads();

    const int mf = wid >> 2;
    const int nfb = (wid & 3) * 3;
    float sc[3][4];
#pragma unroll
    for (int j = 0; j < 3; j++)
#pragma unroll
        for (int q = 0; q < 4; q++) sc[j][q] = 0.f;

#pragma unroll
    for (int kf = 0; kf < 2; kf++) {
        uint32_t qh[4], ql[4];
        uint32_t aoff = (uint32_t)((mf * 16 + lm_row) * QK_ROW) + kf * 32 + lm_chunk;
        LDM_X4(qh, sb + A_QH + aoff);
        LDM_X4(ql, sb + A_QL + aoff);
#pragma unroll
        for (int j = 0; j < 3; j++) {
            uint32_t kk[2];
            uint32_t boff = (uint32_t)(((nfb + j) * 8 + (lane & 7)) * QK_ROW) + kf * 32 +
                            (((lane >> 3) & 1) * 16);
            LDM_X2(kk, sb + A_K + boff);
            MMA_F16(sc[j], qh, kk);
            MMA_F16(sc[j], ql, kk);
        }
    }

    const float rsC = 0.17677669529663689f;
    const int r0 = mf * 16 + (lane >> 2);
    const int r1 = r0 + 8;
    float sv[3][4];
#pragma unroll
    for (int j = 0; j < 3; j++) {
        int nb = (nfb + j) * 8 + (lane & 3) * 2;
#pragma unroll
        for (int q = 0; q < 4; q++) {
            int n = nb + (q & 1);
            int row = (q < 2) ? r0 : r1;
            int t = s0 - 32 + n;
            bool ok = (n >= row) && (n <= row + 64) && (t >= 0) && (t < S_);
            sv[j][q] = ok ? sc[j][q] * rsC : -1e30f;
        }
    }
    float m0 = -1e30f, m1 = -1e30f;
#pragma unroll
    for (int j = 0; j < 3; j++) {
        m0 = fmaxf(m0, fmaxf(sv[j][0], sv[j][1]));
        m1 = fmaxf(m1, fmaxf(sv[j][2], sv[j][3]));
    }
    m0 = fmaxf(m0, __shfl_xor_sync(0xffffffffu, m0, 1));
    m0 = fmaxf(m0, __shfl_xor_sync(0xffffffffu, m0, 2));
    m1 = fmaxf(m1, __shfl_xor_sync(0xffffffffu, m1, 1));
    m1 = fmaxf(m1, __shfl_xor_sync(0xffffffffu, m1, 2));
    if ((lane & 3) == 0) {
        red[r0 * 8 + (wid & 3)] = m0;
        red[r1 * 8 + (wid & 3)] = m1;
    }
    __syncthreads();
    float mx0 = fmaxf(fmaxf(red[r0 * 8 + 0], red[r0 * 8 + 1]),
                      fmaxf(red[r0 * 8 + 2], red[r0 * 8 + 3]));
    float mx1 = fmaxf(fmaxf(red[r1 * 8 + 0], red[r1 * 8 + 1]),
                      fmaxf(red[r1 * 8 + 2], red[r1 * 8 + 3]));
    float e[3][4], sum0 = 0.f, sum1 = 0.f;
#pragma unroll
    for (int j = 0; j < 3; j++) {
        e[j][0] = __expf(sv[j][0] - mx0);
        e[j][1] = __expf(sv[j][1] - mx0);
        e[j][2] = __expf(sv[j][2] - mx1);
        e[j][3] = __expf(sv[j][3] - mx1);
        sum0 += e[j][0] + e[j][1];
        sum1 += e[j][2] + e[j][3];
    }
    sum0 += __shfl_xor_sync(0xffffffffu, sum0, 1);
    sum0 += __shfl_xor_sync(0xffffffffu, sum0, 2);
    sum1 += __shfl_xor_sync(0xffffffffu, sum1, 1);
    sum1 += __shfl_xor_sync(0xffffffffu, sum1, 2);
    if ((lane & 3) == 0) {
        red[r0 * 8 + 4 + (wid & 3)] = sum0;
        red[r1 * 8 + 4 + (wid & 3)] = sum1;
    }
    __syncthreads();
    float inv0 = 1.f / (red[r0 * 8 + 4] + red[r0 * 8 + 5] + red[r0 * 8 + 6] + red[r0 * 8 + 7]);
    float inv1 = 1.f / (red[r1 * 8 + 4] + red[r1 * 8 + 5] + red[r1 * 8 + 6] + red[r1 * 8 + 7]);

#pragma unroll
    for (int j = 0; j < 3; j++) {
        int nb = (nfb + j) * 8 + (lane & 3) * 2;
        uint32_t h0, l0, h1, l1;
        split2h(e[j][0] * inv0, e[j][1] * inv0, h0, l0);
        split2h(e[j][2] * inv1, e[j][3] * inv1, h1, l1);
        *reinterpret_cast<uint32_t*>(sm + A_PH + r0 * VT_ROW + nb * 2) = h0;
        *reinterpret_cast<uint32_t*>(sm + A_PL + r0 * VT_ROW + nb * 2) = l0;
        *reinterpret_cast<uint32_t*>(sm + A_PH + r1 * VT_ROW + nb * 2) = h1;
        *reinterpret_cast<uint32_t*>(sm + A_PL + r1 * VT_ROW + nb * 2) = l1;
    }
    __syncthreads();

    const int nc = wid & 3;
    float oaccH[4] = {0.f, 0.f, 0.f, 0.f};
    float oaccL[4] = {0.f, 0.f, 0.f, 0.f};
#pragma unroll
    for (int kf = 0; kf < 6; kf++) {
        uint32_t ph[4], pl[4], vv[2];
        uint32_t poff = (uint32_t)((mf * 16 + lm_row) * VT_ROW) + kf * 32 + lm_chunk;
        LDM_X4(ph, sb + A_PH + poff);
        LDM_X4(pl, sb + A_PL + poff);
        uint32_t voff = (uint32_t)((kf * 16 + (lane & 15)) * QK_ROW) + nc * 16;
        LDM_X2_T(vv, sb + A_V + voff);
        MMA_F16(oaccH, ph, vv);
        MMA_F16(oaccL, pl, vv);
    }

    {
        int gcol = h * 32 + nc * 8 + (lane & 3) * 2;
        size_t e0 = (size_t)(b * S_ + s0 + r0) * 256 + gcol;
        size_t e1 = (size_t)(b * S_ + s0 + r1) * 256 + gcol;
        float2 gA = *reinterpret_cast<const float2*>(g_G + e0);
        float2 gB = *reinterpret_cast<const float2*>(g_G + e1);
        __half2 o0 = __floats2half2_rn((oaccH[0] + oaccL[0]) * gA.x, (oaccH[1] + oaccL[1]) * gA.y);
        __half2 o1 = __floats2half2_rn((oaccH[2] + oaccL[2]) * gB.x, (oaccH[3] + oaccL[3]) * gB.y);
        *reinterpret_cast<uint32_t*>(g_O + e0) = *reinterpret_cast<uint32_t*>(&o0);
        *reinterpret_cast<uint32_t*>(g_O + e1) = *reinterpret_cast<uint32_t*>(&o1);
    }
}

// ============================================================
extern "C" void kernel_launch(void* const* d_in, const int* in_sizes, int n_in,
                              void* d_out, int out_size) {
    const float* Qin = (const float*)d_in[0];
    const float* Kin = (const float*)d_in[1];
    const float* Vin = (const float*)d_in[2];
    const float* QT  = (const float*)d_in[3];
    const float* KT  = (const float*)d_in[4];
    const float* VT  = (const float*)d_in[5];
    const float* GW  = (const float*)d_in[6];
    const float* Gb  = (const float*)d_in[7];
    const float* OW  = (const float*)d_in[8];
    const float* Ob  = (const float*)d_in[9];
    float* out = (float*)d_out;

    cudaFuncSetAttribute(proj_kernel, cudaFuncAttributeMaxDynamicSharedMemorySize, SMEM_GEMM);
    cudaFuncSetAttribute(out_kernel,  cudaFuncAttributeMaxDynamicSharedMemorySize, SMEM_GEMM);

    prep_w<<<192, 256>>>(QT, KT, VT);
    proj_kernel<<<dim3(4, 64, 4), 256, SMEM_GEMM>>>(Qin, Kin, Vin, GW, Gb);
    attn_kernel<<<dim3(S_ / 32, H_, B_), 256>>>();
    out_kernel<<<dim3(4, 64, 1), 256, SMEM_GEMM>>>(OW, Ob, out);
}

// round 17
// speedup vs baseline: 1.0410x; 1.0410x over previous
#include <cuda_runtime.h>
#include <cuda_fp16.h>
#include <math.h>
#include <stdint.h>

#define B_  2
#define S_  2048
#define D_  256
#define H_  8
#define C_  32
#define OUT_ 256
#define WIN_ 32
#define M_  (B_ * S_)

// -------- device scratch --------
__device__ __align__(16) __half g_X [3 * M_ * D_];
__device__ __align__(16) __half g_Wh[5 * 256 * 256];
__device__ __align__(16) __half g_Wl[5 * 256 * 256];
__device__ __align__(16) __half g_Qh[M_ * D_], g_Ql[M_ * D_];
__device__ __align__(16) __half g_K [M_ * D_];
__device__ __align__(16) __half g_V [M_ * D_];
__device__ __align__(16) float  g_G [M_ * D_];
__device__ __align__(16) __half g_O [M_ * D_];

// ================= helpers =================
__device__ __forceinline__ uint32_t smem_u32(const void* p) {
    uint32_t a;
    asm("{ .reg .u64 t; cvta.to.shared.u64 t, %1; cvt.u32.u64 %0, t; }" : "=r"(a) : "l"(p));
    return a;
}
#define LDM_X4(r, addr) \
    asm volatile("ldmatrix.sync.aligned.m8n8.x4.shared.b16 {%0,%1,%2,%3}, [%4];" \
        : "=r"((r)[0]), "=r"((r)[1]), "=r"((r)[2]), "=r"((r)[3]) : "r"(addr))
#define LDM_X2(r, addr) \
    asm volatile("ldmatrix.sync.aligned.m8n8.x2.shared.b16 {%0,%1}, [%2];" \
        : "=r"((r)[0]), "=r"((r)[1]) : "r"(addr))
#define LDM_X2_T(r, addr) \
    asm volatile("ldmatrix.sync.aligned.m8n8.x2.trans.shared.b16 {%0,%1}, [%2];" \
        : "=r"((r)[0]), "=r"((r)[1]) : "r"(addr))
#define MMA_F16(c, a, b) \
    asm volatile("mma.sync.aligned.m16n8k16.row.col.f32.f16.f16.f32 " \
        "{%0,%1,%2,%3}, {%4,%5,%6,%7}, {%8,%9}, {%0,%1,%2,%3};" \
        : "+f"((c)[0]), "+f"((c)[1]), "+f"((c)[2]), "+f"((c)[3]) \
        : "r"((a)[0]), "r"((a)[1]), "r"((a)[2]), "r"((a)[3]), "r"((b)[0]), "r"((b)[1]))
#define CP_ASYNC16(dst, src) \
    asm volatile("cp.async.cg.shared.global [%0], [%1], 16;" :: "r"(dst), "l"(src))
#define CP_COMMIT() asm volatile("cp.async.commit_group;" ::: "memory")
#define CP_WAIT(n)  asm volatile("cp.async.wait_group %0;" :: "n"(n) : "memory")

#define GRID_DEP_WAIT()   asm volatile("griddepcontrol.wait;" ::: "memory")
#define GRID_DEP_LAUNCH() asm volatile("griddepcontrol.launch_dependents;" ::: "memory")

__device__ __forceinline__ void split2h(float a, float b, uint32_t& h, uint32_t& l) {
    __half2 hi2 = __floats2half2_rn(a, b);
    float ra = a - __low2float(hi2);
    float rb = b - __high2float(hi2);
    __half2 lo2 = __floats2half2_rn(ra, rb);
    h = *reinterpret_cast<uint32_t*>(&hi2);
    l = *reinterpret_cast<uint32_t*>(&lo2);
}

// ================= fused prep kernel (R9) =================
__global__ void prep_all(const float* __restrict__ Qin, const float* __restrict__ Kin,
                         const float* __restrict__ Vin, const float* __restrict__ QT,
                         const float* __restrict__ KT,  const float* __restrict__ VT,
                         const float* __restrict__ GW,  const float* __restrict__ OW) {
    int blk = blockIdx.x;
    if (blk < 3072) {
        int z = blk >> 10;
        int bx = blk & 1023;
        const float* src = (z == 0) ? Qin : (z == 1) ? Kin : Vin;
        size_t base = (size_t)z * (M_ * D_);
        int i = bx * 256 + threadIdx.x;
        float4 v = reinterpret_cast<const float4*>(src)[i];
        __half2 a = __floats2half2_rn(v.x, v.y);
        __half2 b = __floats2half2_rn(v.z, v.w);
        reinterpret_cast<uint2*>(g_X + base)[i] =
            make_uint2(*reinterpret_cast<uint32_t*>(&a), *reinterpret_cast<uint32_t*>(&b));
    } else if (blk < 3200) {
        int t = blk - 3072;
        int z = t >> 6;
        int bx = t & 63;
        const float* src = (z == 0) ? GW : OW;
        size_t base = (size_t)(3 + z) * 65536;
        int i = bx * 256 + threadIdx.x;
        float4 v = reinterpret_cast<const float4*>(src)[i];
        uint32_t h0, l0, h1, l1;
        split2h(v.x, v.y, h0, l0);
        split2h(v.z, v.w, h1, l1);
        reinterpret_cast<uint2*>(g_Wh + base)[i] = make_uint2(h0, h1);
        reinterpret_cast<uint2*>(g_Wl + base)[i] = make_uint2(l0, l1);
    } else {
        int t = blk - 3200;
        int z = t >> 6;
        int ky = (t >> 3) & 7;
        int nx = t & 7;
        const float* src = (z == 0) ? QT : (z == 1) ? KT : VT;
        size_t base = (size_t)z * 65536;
        __shared__ float tr[32][33];
        int tx = threadIdx.x & 31, ty = threadIdx.x >> 5;
        int k0 = ky * 32, n0 = nx * 32;
#pragma unroll
        for (int r = 0; r < 4; r++)
            tr[ty + r * 8][tx] = src[(size_t)(k0 + ty + r * 8) * 256 + n0 + tx];
        __syncthreads();
#pragma unroll
        for (int r = 0; r < 4; r++) {
            int n = n0 + ty + r * 8, k = k0 + tx;
            float v = tr[tx][ty + r * 8];
            __half h = __float2half(v);
            g_Wh[base + (size_t)n * 256 + k] = h;
            g_Wl[base + (size_t)n * 256 + k] = __float2half(v - __half2float(h));
        }
    }
    GRID_DEP_LAUNCH();   // trigger proj only as we drain
}

// ================= fp16 MMA GEMM: BK=128, both chunks fully prefetched (R9) =================
#define G_ROW  272
#define GBM    64
#define GBN    64
#define STAGE_ ((GBM + 2 * GBN) * G_ROW)
#define SMEM_GEMM (2 * STAGE_)

// MODE: 0 = split half out, 1 = f32+bias+sigmoid, 2 = f32+bias, 3 = single half out
template <int MODE>
__device__ __forceinline__ void gemm_core(const __half* __restrict__ A,
                                          const __half* __restrict__ Bh, const __half* __restrict__ Bl,
                                          const float* __restrict__ bias,
                                          float* __restrict__ Yf,
                                          __half* __restrict__ Yh, __half* __restrict__ Yl) {
    extern __shared__ char smem[];
    const uint32_t sb = smem_u32(smem);
    const int tid = threadIdx.x, wid = tid >> 5, lane = tid & 31;

    const int warp_m = wid & 1, warp_n = wid >> 1;
    const int m0 = blockIdx.y * GBM, n0 = blockIdx.x * GBN;
    const int lm_row = lane & 15, lm_chunk = (lane >> 4) * 16;

    float acc[2][2][4];
#pragma unroll
    for (int i = 0; i < 2; i++)
#pragma unroll
        for (int j = 0; j < 2; j++)
#pragma unroll
            for (int q = 0; q < 4; q++) acc[i][j][q] = 0.f;

    auto stage = [&](int kc, int buf) {
#pragma unroll
        for (int task = tid; task < 3072; task += 256) {
            int row = task >> 4;
            int ch  = task & 15;
            const __half* s;
            uint32_t dbase;
            if (row < GBM) {
                s = A + (size_t)(m0 + row) * 256 + kc * 128 + ch * 8;
                dbase = (uint32_t)(row * G_ROW);
            } else if (row < GBM + GBN) {
                int r = row - GBM;
                s = Bh + (size_t)(n0 + r) * 256 + kc * 128 + ch * 8;
                dbase = (uint32_t)((GBM + r) * G_ROW);
            } else {
                int r = row - GBM - GBN;
                s = Bl + (size_t)(n0 + r) * 256 + kc * 128 + ch * 8;
                dbase = (uint32_t)((GBM + GBN + r) * G_ROW);
            }
            CP_ASYNC16(sb + buf * STAGE_ + dbase + ch * 16, s);
        }
    };

    stage(0, 0); CP_COMMIT();
    stage(1, 1); CP_COMMIT();

#pragma unroll
    for (int kc = 0; kc < 2; kc++) {
        if (kc == 0) CP_WAIT(1); else CP_WAIT(0);
        __syncthreads();

        const uint32_t bb = sb + kc * STAGE_;
#pragma unroll
        for (int ks = 0; ks < 8; ks++) {
            const uint32_t kbyte = ks * 32 + lm_chunk;
            uint32_t a[2][4], bh[2][2], bl[2][2];
#pragma unroll
            for (int mf = 0; mf < 2; mf++) {
                uint32_t off = (uint32_t)((warp_m * 32 + mf * 16 + lm_row) * G_ROW) + kbyte;
                LDM_X4(a[mf], bb + off);
            }
            {
                uint32_t off = (uint32_t)((warp_n * 16 + lm_row) * G_ROW) + kbyte;
                uint32_t th[4], tl[4];
                LDM_X4(th, bb + GBM * G_ROW + off);
                LDM_X4(tl, bb + (GBM + GBN) * G_ROW + off);
                bh[0][0] = th[0]; bh[0][1] = th[2];
                bh[1][0] = th[1]; bh[1][1] = th[3];
                bl[0][0] = tl[0]; bl[0][1] = tl[2];
                bl[1][0] = tl[1]; bl[1][1] = tl[3];
            }
#pragma unroll
            for (int mf = 0; mf < 2; mf++)
#pragma unroll
                for (int nf = 0; nf < 2; nf++) {
                    MMA_F16(acc[mf][nf], a[mf], bh[nf]);
                    MMA_F16(acc[mf][nf], a[mf], bl[nf]);
                }
        }
    }

    // epilogue
#pragma unroll
    for (int mf = 0; mf < 2; mf++) {
        int row = m0 + warp_m * 32 + mf * 16 + (lane >> 2);
#pragma unroll
        for (int nf = 0; nf < 2; nf++) {
            int col = n0 + warp_n * 16 + nf * 8 + (lane & 3) * 2;
            float v0 = acc[mf][nf][0], v1 = acc[mf][nf][1];
            float v2 = acc[mf][nf][2], v3 = acc[mf][nf][3];
            if (MODE == 1 || MODE == 2) {
                float b0 = bias[col], b1 = bias[col + 1];
                v0 += b0; v1 += b1; v2 += b0; v3 += b1;
                if (MODE == 1) {
                    v0 = 1.f / (1.f + __expf(-v0));
                    v1 = 1.f / (1.f + __expf(-v1));
                    v2 = 1.f / (1.f + __expf(-v2));
                    v3 = 1.f / (1.f + __expf(-v3));
                }
                *reinterpret_cast<float2*>(Yf + (size_t)row * 256 + col)       = make_float2(v0, v1);
                *reinterpret_cast<float2*>(Yf + (size_t)(row + 8) * 256 + col) = make_float2(v2, v3);
            } else if (MODE == 0) {
                uint32_t h0, l0, h1, l1;
                split2h(v0, v1, h0, l0);
                split2h(v2, v3, h1, l1);
                *reinterpret_cast<uint32_t*>(Yh + (size_t)row * 256 + col)       = h0;
                *reinterpret_cast<uint32_t*>(Yl + (size_t)row * 256 + col)       = l0;
                *reinterpret_cast<uint32_t*>(Yh + (size_t)(row + 8) * 256 + col) = h1;
                *reinterpret_cast<uint32_t*>(Yl + (size_t)(row + 8) * 256 + col) = l1;
            } else {
                __half2 a2 = __floats2half2_rn(v0, v1);
                __half2 b2 = __floats2half2_rn(v2, v3);
                *reinterpret_cast<uint32_t*>(Yh + (size_t)row * 256 + col)       = *reinterpret_cast<uint32_t*>(&a2);
                *reinterpret_cast<uint32_t*>(Yh + (size_t)(row + 8) * 256 + col) = *reinterpret_cast<uint32_t*>(&b2);
            }
        }
    }
}

__global__ void __launch_bounds__(256, 2)
proj_kernel(const float* __restrict__ Gb) {
    GRID_DEP_WAIT();
    int z = blockIdx.z;
    int xslot = (z == 3) ? 2 : z;
    const __half* A  = g_X + (size_t)xslot * (M_ * D_);
    const __half* Bh = g_Wh + (size_t)z * 65536;
    const __half* Bl = g_Wl + (size_t)z * 65536;
    if (z == 0)      gemm_core<0>(A, Bh, Bl, nullptr, nullptr, g_Qh, g_Ql);
    else if (z == 1) gemm_core<3>(A, Bh, Bl, nullptr, nullptr, g_K, nullptr);
    else if (z == 2) gemm_core<3>(A, Bh, Bl, nullptr, nullptr, g_V, nullptr);
    else             gemm_core<1>(A, Bh, Bl, Gb, g_G, nullptr, nullptr);
    GRID_DEP_LAUNCH();   // trigger attn during drain
}

__global__ void __launch_bounds__(256, 2)
out_kernel(const float* __restrict__ Ob, float* __restrict__ out) {
    GRID_DEP_WAIT();
    gemm_core<2>(g_O, g_Wh + 4 * 65536, g_Wl + 4 * 65536, Ob, out, nullptr, nullptr);
}

// ================= fp16 tensor-core local-window attention (R9) =================
#define A_QH 0
#define A_QL 2560
#define A_K  5120
#define A_V  12800
#define A_PH 20480
#define A_PL 27136
#define A_RED 33792
#define A_TOTAL 34816
#define QK_ROW 80
#define VT_ROW 208

__global__ void __launch_bounds__(256)
attn_kernel() {
    GRID_DEP_WAIT();
    __shared__ __align__(16) char sm[A_TOTAL];
    const uint32_t sb = smem_u32(sm);
    float* red = reinterpret_cast<float*>(sm + A_RED);

    const int b = blockIdx.z, h = blockIdx.y, s0 = blockIdx.x * 32;
    const int tid = threadIdx.x, wid = tid >> 5, lane = tid & 31;
    const int lm_row = lane & 15, lm_chunk = (lane >> 4) * 16;

    for (int i = tid; i < 384; i += 256) {
        int row = i >> 2, ch = i & 3;
        int t = s0 - 32 + row;
        uint4 vk = make_uint4(0, 0, 0, 0), vv = vk;
        if (t >= 0 && t < S_) {
            size_t e = (size_t)(b * S_ + t) * 256 + h * 32 + ch * 8;
            vk = *reinterpret_cast<const uint4*>(g_K + e);
            vv = *reinterpret_cast<const uint4*>(g_V + e);
        }
        *reinterpret_cast<uint4*>(sm + A_K + row * QK_ROW + ch * 16) = vk;
        *reinterpret_cast<uint4*>(sm + A_V + row * QK_ROW + ch * 16) = vv;
    }
    for (int i = tid; i < 128; i += 256) {
        int row = i >> 2, ch = i & 3;
        size_t e = (size_t)(b * S_ + s0 + row) * 256 + h * 32 + ch * 8;
        *reinterpret_cast<uint4*>(sm + A_QH + row * QK_ROW + ch * 16) =
            *reinterpret_cast<const uint4*>(g_Qh + e);
        *reinterpret_cast<uint4*>(sm + A_QL + row * QK_ROW + ch * 16) =
            *reinterpret_cast<const uint4*>(g_Ql + e);
    }
    __syncthreads();

    const int mf = wid >> 2;
    const int nfb = (wid & 3) * 3;
    float sc[3][4];
#pragma unroll
    for (int j = 0; j < 3; j++)
#pragma unroll
        for (int q = 0; q < 4; q++) sc[j][q] = 0.f;

#pragma unroll
    for (int kf = 0; kf < 2; kf++) {
        uint32_t qh[4], ql[4];
        uint32_t aoff = (uint32_t)((mf * 16 + lm_row) * QK_ROW) + kf * 32 + lm_chunk;
        LDM_X4(qh, sb + A_QH + aoff);
        LDM_X4(ql, sb + A_QL + aoff);
#pragma unroll
        for (int j = 0; j < 3; j++) {
            uint32_t kk[2];
            uint32_t boff = (uint32_t)(((nfb + j) * 8 + (lane & 7)) * QK_ROW) + kf * 32 +
                            (((lane >> 3) & 1) * 16);
            LDM_X2(kk, sb + A_K + boff);
            MMA_F16(sc[j], qh, kk);
            MMA_F16(sc[j], ql, kk);
        }
    }

    const float rsC = 0.17677669529663689f;
    const int r0 = mf * 16 + (lane >> 2);
    const int r1 = r0 + 8;
    float sv[3][4];
#pragma unroll
    for (int j = 0; j < 3; j++) {
        int nb = (nfb + j) * 8 + (lane & 3) * 2;
#pragma unroll
        for (int q = 0; q < 4; q++) {
            int n = nb + (q & 1);
            int row = (q < 2) ? r0 : r1;
            int t = s0 - 32 + n;
            bool ok = (n >= row) && (n <= row + 64) && (t >= 0) && (t < S_);
            sv[j][q] = ok ? sc[j][q] * rsC : -1e30f;
        }
    }
    float m0 = -1e30f, m1 = -1e30f;
#pragma unroll
    for (int j = 0; j < 3; j++) {
        m0 = fmaxf(m0, fmaxf(sv[j][0], sv[j][1]));
        m1 = fmaxf(m1, fmaxf(sv[j][2], sv[j][3]));
    }
    m0 = fmaxf(m0, __shfl_xor_sync(0xffffffffu, m0, 1));
    m0 = fmaxf(m0, __shfl_xor_sync(0xffffffffu, m0, 2));
    m1 = fmaxf(m1, __shfl_xor_sync(0xffffffffu, m1, 1));
    m1 = fmaxf(m1, __shfl_xor_sync(0xffffffffu, m1, 2));
    if ((lane & 3) == 0) {
        red[r0 * 8 + (wid & 3)] = m0;
        red[r1 * 8 + (wid & 3)] = m1;
    }
    __syncthreads();
    float mx0 = fmaxf(fmaxf(red[r0 * 8 + 0], red[r0 * 8 + 1]),
                      fmaxf(red[r0 * 8 + 2], red[r0 * 8 + 3]));
    float mx1 = fmaxf(fmaxf(red[r1 * 8 + 0], red[r1 * 8 + 1]),
                      fmaxf(red[r1 * 8 + 2], red[r1 * 8 + 3]));
    float e[3][4], sum0 = 0.f, sum1 = 0.f;
#pragma unroll
    for (int j = 0; j < 3; j++) {
        e[j][0] = __expf(sv[j][0] - mx0);
        e[j][1] = __expf(sv[j][1] - mx0);
        e[j][2] = __expf(sv[j][2] - mx1);
        e[j][3] = __expf(sv[j][3] - mx1);
        sum0 += e[j][0] + e[j][1];
        sum1 += e[j][2] + e[j][3];
    }
    sum0 += __shfl_xor_sync(0xffffffffu, sum0, 1);
    sum0 += __shfl_xor_sync(0xffffffffu, sum0, 2);
    sum1 += __shfl_xor_sync(0xffffffffu, sum1, 1);
    sum1 += __shfl_xor_sync(0xffffffffu, sum1, 2);
    if ((lane & 3) == 0) {
        red[r0 * 8 + 4 + (wid & 3)] = sum0;
        red[r1 * 8 + 4 + (wid & 3)] = sum1;
    }
    __syncthreads();
    float inv0 = 1.f / (red[r0 * 8 + 4] + red[r0 * 8 + 5] + red[r0 * 8 + 6] + red[r0 * 8 + 7]);
    float inv1 = 1.f / (red[r1 * 8 + 4] + red[r1 * 8 + 5] + red[r1 * 8 + 6] + red[r1 * 8 + 7]);

#pragma unroll
    for (int j = 0; j < 3; j++) {
        int nb = (nfb + j) * 8 + (lane & 3) * 2;
        uint32_t h0, l0, h1, l1;
        split2h(e[j][0] * inv0, e[j][1] * inv0, h0, l0);
        split2h(e[j][2] * inv1, e[j][3] * inv1, h1, l1);
        *reinterpret_cast<uint32_t*>(sm + A_PH + r0 * VT_ROW + nb * 2) = h0;
        *reinterpret_cast<uint32_t*>(sm + A_PL + r0 * VT_ROW + nb * 2) = l0;
        *reinterpret_cast<uint32_t*>(sm + A_PH + r1 * VT_ROW + nb * 2) = h1;
        *reinterpret_cast<uint32_t*>(sm + A_PL + r1 * VT_ROW + nb * 2) = l1;
    }
    __syncthreads();

    const int nc = wid & 3;
    float oaccH[4] = {0.f, 0.f, 0.f, 0.f};
    float oaccL[4] = {0.f, 0.f, 0.f, 0.f};
#pragma unroll
    for (int kf = 0; kf < 6; kf++) {
        uint32_t ph[4], pl[4], vv[2];
        uint32_t poff = (uint32_t)((mf * 16 + lm_row) * VT_ROW) + kf * 32 + lm_chunk;
        LDM_X4(ph, sb + A_PH + poff);
        LDM_X4(pl, sb + A_PL + poff);
        uint32_t voff = (uint32_t)((kf * 16 + (lane & 15)) * QK_ROW) + nc * 16;
        LDM_X2_T(vv, sb + A_V + voff);
        MMA_F16(oaccH, ph, vv);
        MMA_F16(oaccL, pl, vv);
    }

    {
        int gcol = h * 32 + nc * 8 + (lane & 3) * 2;
        size_t e0 = (size_t)(b * S_ + s0 + r0) * 256 + gcol;
        size_t e1 = (size_t)(b * S_ + s0 + r1) * 256 + gcol;
        float2 gA = *reinterpret_cast<const float2*>(g_G + e0);
        float2 gB = *reinterpret_cast<const float2*>(g_G + e1);
        __half2 o0 = __floats2half2_rn((oaccH[0] + oaccL[0]) * gA.x, (oaccH[1] + oaccL[1]) * gA.y);
        __half2 o1 = __floats2half2_rn((oaccH[2] + oaccL[2]) * gB.x, (oaccH[3] + oaccL[3]) * gB.y);
        *reinterpret_cast<uint32_t*>(g_O + e0) = *reinterpret_cast<uint32_t*>(&o0);
        *reinterpret_cast<uint32_t*>(g_O + e1) = *reinterpret_cast<uint32_t*>(&o1);
    }
    GRID_DEP_LAUNCH();   // trigger out during drain
}

// ============================================================
extern "C" void kernel_launch(void* const* d_in, const int* in_sizes, int n_in,
                              void* d_out, int out_size) {
    const float* Qin = (const float*)d_in[0];
    const float* Kin = (const float*)d_in[1];
    const float* Vin = (const float*)d_in[2];
    const float* QT  = (const float*)d_in[3];
    const float* KT  = (const float*)d_in[4];
    const float* VT  = (const float*)d_in[5];
    const float* GW  = (const float*)d_in[6];
    const float* Gb  = (const float*)d_in[7];
    const float* OW  = (const float*)d_in[8];
    const float* Ob  = (const float*)d_in[9];
    float* out = (float*)d_out;

    cudaFuncSetAttribute(proj_kernel, cudaFuncAttributeMaxDynamicSharedMemorySize, SMEM_GEMM);
    cudaFuncSetAttribute(out_kernel,  cudaFuncAttributeMaxDynamicSharedMemorySize, SMEM_GEMM);

    prep_all<<<3392, 256>>>(Qin, Kin, Vin, QT, KT, VT, GW, OW);

    cudaLaunchAttribute attr[1];
    attr[0].id = cudaLaunchAttributeProgrammaticStreamSerialization;
    attr[0].val.programmaticStreamSerializationAllowed = 1;

    {
        cudaLaunchConfig_t cfg = {};
        cfg.gridDim = dim3(4, 64, 4);
        cfg.blockDim = dim3(256, 1, 1);
        cfg.dynamicSmemBytes = SMEM_GEMM;
        cfg.attrs = attr;
        cfg.numAttrs = 1;
        cudaLaunchKernelEx(&cfg, proj_kernel, Gb);
    }
    {
        cudaLaunchConfig_t cfg = {};
        cfg.gridDim = dim3(S_ / 32, H_, B_);
        cfg.blockDim = dim3(256, 1, 1);
        cfg.dynamicSmemBytes = 0;
        cfg.attrs = attr;
        cfg.numAttrs = 1;
        cudaLaunchKernelEx(&cfg, attn_kernel);
    }
    {
        cudaLaunchConfig_t cfg = {};
        cfg.gridDim = dim3(4, 64, 1);
        cfg.blockDim = dim3(256, 1, 1);
        cfg.dynamicSmemBytes = SMEM_GEMM;
        cfg.attrs = attr;
        cfg.numAttrs = 1;
        cudaLaunchKernelEx(&cfg, out_kernel, Ob, out);
    }
}